// round 2
// baseline (speedup 1.0000x reference)
#include <cuda_runtime.h>
#include <cstdint>

#define NB 8
#define NN 4096
#define NM 1024
#define ND 256

// ---------------- scratch (device globals; no runtime allocation) ----------------
static constexpr size_t OFF_WHT = 0;
static constexpr size_t OFF_WLT = OFF_WHT + (size_t)ND * ND;
static constexpr size_t OFF_WGT = OFF_WLT + (size_t)ND * ND;
static constexpr size_t OFF_H   = OFF_WGT + (size_t)ND * ND;
static constexpr size_t OFF_L   = OFF_H  + (size_t)NB * NN * ND;
static constexpr size_t OFF_G   = OFF_L  + (size_t)NB * NM * ND;
static constexpr size_t OFF_GT  = OFF_G  + (size_t)NB * NM * ND;
static constexpr size_t OFF_S   = OFF_GT + (size_t)NB * ND * NM;
static constexpr size_t SCRATCH_TOTAL = OFF_S + (size_t)NB * NN * NM;

__device__ float g_scratch[SCRATCH_TOTAL];

// ---------------- helpers ----------------
__device__ __forceinline__ uint32_t f2tf(float x) {
    uint32_t r;
    asm("cvt.rna.tf32.f32 %0, %1;" : "=r"(r) : "f"(x));
    return r;
}

#define MMA8(d, a, b)                                                          \
    asm volatile(                                                              \
        "mma.sync.aligned.m16n8k8.row.col.f32.tf32.tf32.f32 "                  \
        "{%0,%1,%2,%3},{%4,%5,%6,%7},{%8,%9},{%0,%1,%2,%3};\n"                 \
        : "+f"((d)[0]), "+f"((d)[1]), "+f"((d)[2]), "+f"((d)[3])               \
        : "r"((a)[0]), "r"((a)[1]), "r"((a)[2]), "r"((a)[3]),                  \
          "r"((b)[0]), "r"((b)[1]))

// ---------------- weight transpose: WT[n][k] = W[k][n] ----------------
__global__ void transpose_w_k(const float* __restrict__ Wh,
                              const float* __restrict__ Wl,
                              const float* __restrict__ Wg,
                              float* __restrict__ wht,
                              float* __restrict__ wlt,
                              float* __restrict__ wgt) {
    int i = blockIdx.x * blockDim.x + threadIdx.x;  // 65536 total
    int n = i >> 8, k = i & 255;
    wht[i] = Wh[k * ND + n];
    wlt[i] = Wl[k * ND + n];
    wgt[i] = Wg[k * ND + n];
}

// ---------------- G transpose: GT[b][d][m] = G[b][m][d] ----------------
__global__ void transpose_g_k(const float* __restrict__ G, float* __restrict__ GT) {
    __shared__ float t[32][33];
    int b = blockIdx.z;
    int m0 = blockIdx.x * 32, d0 = blockIdx.y * 32;
    const float* src = G + (size_t)b * NM * ND;
    float* dst = GT + (size_t)b * ND * NM;
    int x = threadIdx.x, y = threadIdx.y;
#pragma unroll
    for (int i = 0; i < 32; i += 8) t[y + i][x] = src[(size_t)(m0 + y + i) * ND + d0 + x];
    __syncthreads();
#pragma unroll
    for (int i = 0; i < 32; i += 8) dst[(size_t)(d0 + y + i) * NM + m0 + x] = t[x][y + i];
}

// ---------------- generic TT GEMM: C[row][col] = sum_k A[row][k] * Bsrc[col][k] ----------------
// A: [rows][K] row-major, Bsrc: [Ncols][K] row-major (both loaded identically).
// SPLIT: split-tf32 (3-MMA hi/lo) for ~fp32 accuracy. BIAS: +bias[col]. RESID: +R[row][col].
template <bool SPLIT, bool BIAS, bool RESID>
__global__ void __launch_bounds__(256)
gemm_tt(const float* __restrict__ Aptr, const float* __restrict__ Bptr,
        const float* __restrict__ bias, const float* __restrict__ Rptr,
        float* __restrict__ Cptr, int K, int Ncols,
        long long sA, long long sB, long long sC) {
    constexpr int BM = 128, BN = 128, BK = 32, LDSR = 36;  // pad -> conflict-free frag LDS
    extern __shared__ uint32_t smem_u[];
    uint32_t* As = smem_u;
    uint32_t* Bs = smem_u + BM * LDSR;
    uint32_t* Al = smem_u + 2 * BM * LDSR;  // only used when SPLIT
    uint32_t* Bl = smem_u + 3 * BM * LDSR;

    int tid = threadIdx.x;
    int lane = tid & 31, wid = tid >> 5;
    int wm = wid >> 1, wn = wid & 1;     // 4x2 warp grid; warp tile 32x64
    int grp = lane >> 2, tq = lane & 3;  // mma fragment coords

    long long zb = blockIdx.z;
    const float* A = Aptr + zb * sA + (long long)blockIdx.x * BM * K;
    const float* Bm = Bptr + zb * sB + (long long)blockIdx.y * BN * K;

    float acc[2][8][4];
#pragma unroll
    for (int i = 0; i < 2; i++)
#pragma unroll
        for (int j = 0; j < 8; j++)
#pragma unroll
            for (int q = 0; q < 4; q++) acc[i][j][q] = 0.f;

    for (int kc = 0; kc < K; kc += BK) {
        __syncthreads();
#pragma unroll
        for (int it = 0; it < 4; it++) {
            int idx = tid + it * 256;
            int rr = idx >> 3, cc = (idx & 7) * 4;
            float4 va = *(const float4*)(A + (long long)rr * K + kc + cc);
            float4 vb = *(const float4*)(Bm + (long long)rr * K + kc + cc);
            uint32_t* pa = As + rr * LDSR + cc;
            uint32_t* pb = Bs + rr * LDSR + cc;
            uint32_t h;
            h = f2tf(va.x); pa[0] = h; if (SPLIT) Al[rr * LDSR + cc + 0] = f2tf(va.x - __uint_as_float(h));
            h = f2tf(va.y); pa[1] = h; if (SPLIT) Al[rr * LDSR + cc + 1] = f2tf(va.y - __uint_as_float(h));
            h = f2tf(va.z); pa[2] = h; if (SPLIT) Al[rr * LDSR + cc + 2] = f2tf(va.z - __uint_as_float(h));
            h = f2tf(va.w); pa[3] = h; if (SPLIT) Al[rr * LDSR + cc + 3] = f2tf(va.w - __uint_as_float(h));
            h = f2tf(vb.x); pb[0] = h; if (SPLIT) Bl[rr * LDSR + cc + 0] = f2tf(vb.x - __uint_as_float(h));
            h = f2tf(vb.y); pb[1] = h; if (SPLIT) Bl[rr * LDSR + cc + 1] = f2tf(vb.y - __uint_as_float(h));
            h = f2tf(vb.z); pb[2] = h; if (SPLIT) Bl[rr * LDSR + cc + 2] = f2tf(vb.z - __uint_as_float(h));
            h = f2tf(vb.w); pb[3] = h; if (SPLIT) Bl[rr * LDSR + cc + 3] = f2tf(vb.w - __uint_as_float(h));
        }
        __syncthreads();
#pragma unroll
        for (int ks = 0; ks < 4; ks++) {
            int k0 = ks * 8;
            uint32_t a[2][4], al[2][4];
            uint32_t b[8][2], bl2[8][2];
#pragma unroll
            for (int i = 0; i < 2; i++) {
                int ro = (wm * 32 + i * 16 + grp) * LDSR + k0 + tq;
                a[i][0] = As[ro];
                a[i][1] = As[ro + 8 * LDSR];
                a[i][2] = As[ro + 4];
                a[i][3] = As[ro + 8 * LDSR + 4];
                if (SPLIT) {
                    al[i][0] = Al[ro];
                    al[i][1] = Al[ro + 8 * LDSR];
                    al[i][2] = Al[ro + 4];
                    al[i][3] = Al[ro + 8 * LDSR + 4];
                }
            }
#pragma unroll
            for (int j = 0; j < 8; j++) {
                int co = (wn * 64 + j * 8 + grp) * LDSR + k0 + tq;
                b[j][0] = Bs[co];
                b[j][1] = Bs[co + 4];
                if (SPLIT) {
                    bl2[j][0] = Bl[co];
                    bl2[j][1] = Bl[co + 4];
                }
            }
#pragma unroll
            for (int i = 0; i < 2; i++)
#pragma unroll
                for (int j = 0; j < 8; j++) {
                    if (SPLIT) {
                        MMA8(acc[i][j], al[i], b[j]);
                        MMA8(acc[i][j], a[i], bl2[j]);
                    }
                    MMA8(acc[i][j], a[i], b[j]);
                }
        }
    }

    // epilogue
    int row0 = blockIdx.x * BM + wm * 32 + grp;
    int col0 = blockIdx.y * BN + wn * 64 + 2 * tq;
    float* C = Cptr + zb * sC;
    const float* R = RESID ? (Rptr + zb * sC) : nullptr;
#pragma unroll
    for (int i = 0; i < 2; i++) {
#pragma unroll
        for (int j = 0; j < 8; j++) {
            int row = row0 + i * 16;
            int col = col0 + j * 8;
            float2 v0 = make_float2(acc[i][j][0], acc[i][j][1]);
            float2 v1 = make_float2(acc[i][j][2], acc[i][j][3]);
            if (BIAS) {
                float2 bb = *(const float2*)(bias + col);
                v0.x += bb.x; v0.y += bb.y;
                v1.x += bb.x; v1.y += bb.y;
            }
            if (RESID) {
                float2 r0 = *(const float2*)(R + (long long)row * Ncols + col);
                float2 r1 = *(const float2*)(R + (long long)(row + 8) * Ncols + col);
                v0.x += r0.x; v0.y += r0.y;
                v1.x += r1.x; v1.y += r1.y;
            }
            *(float2*)(C + (long long)row * Ncols + col) = v0;
            *(float2*)(C + (long long)(row + 8) * Ncols + col) = v1;
        }
    }
}

// ---------------- softmax over M: one warp per row ----------------
__global__ void softmax_k(float* __restrict__ S) {
    int row = blockIdx.x * 8 + (threadIdx.x >> 5);
    int lane = threadIdx.x & 31;
    float4* p4 = (float4*)(S + (size_t)row * NM) + lane;
    float4 v[8];
    float mx = -1e30f;
#pragma unroll
    for (int t = 0; t < 8; t++) {
        v[t] = p4[t * 32];
        mx = fmaxf(mx, fmaxf(fmaxf(v[t].x, v[t].y), fmaxf(v[t].z, v[t].w)));
    }
#pragma unroll
    for (int o = 16; o > 0; o >>= 1) mx = fmaxf(mx, __shfl_xor_sync(0xffffffffu, mx, o));
    float sum = 0.f;
#pragma unroll
    for (int t = 0; t < 8; t++) {
        v[t].x = __expf(v[t].x - mx);
        v[t].y = __expf(v[t].y - mx);
        v[t].z = __expf(v[t].z - mx);
        v[t].w = __expf(v[t].w - mx);
        sum += v[t].x + v[t].y + v[t].z + v[t].w;
    }
#pragma unroll
    for (int o = 16; o > 0; o >>= 1) sum += __shfl_xor_sync(0xffffffffu, sum, o);
    float inv = 1.0f / sum;
#pragma unroll
    for (int t = 0; t < 8; t++) {
        v[t].x *= inv; v[t].y *= inv; v[t].z *= inv; v[t].w *= inv;
        p4[t * 32] = v[t];
    }
}

// ---------------- launch ----------------
extern "C" void kernel_launch(void* const* d_in, const int* in_sizes, int n_in,
                              void* d_out, int out_size) {
    const float* p  = (const float*)d_in[0];
    const float* r  = (const float*)d_in[1];
    // d_in[2] = batch ids (int64) — unused (implied by layout)
    const float* Wh = (const float*)d_in[3];
    const float* bh = (const float*)d_in[4];
    const float* Wl = (const float*)d_in[5];
    const float* bl = (const float*)d_in[6];
    const float* Wg = (const float*)d_in[7];
    const float* bg = (const float*)d_in[8];
    float* out = (float*)d_out;
    (void)in_sizes; (void)n_in; (void)out_size;

    float* s = nullptr;
    cudaGetSymbolAddress((void**)&s, g_scratch);
    float* WhT = s + OFF_WHT;
    float* WlT = s + OFF_WLT;
    float* WgT = s + OFF_WGT;
    float* H   = s + OFF_H;
    float* L   = s + OFF_L;
    float* G   = s + OFF_G;
    float* GT  = s + OFF_GT;
    float* S   = s + OFF_S;

    const int SMEM_SPLIT = 4 * 128 * 36 * 4;  // 73728
    const int SMEM_PLAIN = 2 * 128 * 36 * 4;  // 36864
    cudaFuncSetAttribute(gemm_tt<true, true, false>,
                         cudaFuncAttributeMaxDynamicSharedMemorySize, SMEM_SPLIT);
    cudaFuncSetAttribute(gemm_tt<true, false, false>,
                         cudaFuncAttributeMaxDynamicSharedMemorySize, SMEM_SPLIT);
    cudaFuncSetAttribute(gemm_tt<false, false, true>,
                         cudaFuncAttributeMaxDynamicSharedMemorySize, SMEM_PLAIN);

    // 0. transpose weights -> [n][k]
    transpose_w_k<<<256, 256>>>(Wh, Wl, Wg, WhT, WlT, WgT);

    // 1. H = p @ Wh + bh   (split-tf32; rows = B*N)
    gemm_tt<true, true, false><<<dim3(NB * NN / 128, ND / 128, 1), 256, SMEM_SPLIT>>>(
        p, WhT, bh, nullptr, H, ND, ND, 0, 0, 0);

    // 2. L = r @ Wl + bl   (split-tf32; rows = B*M)
    gemm_tt<true, true, false><<<dim3(NB * NM / 128, ND / 128, 1), 256, SMEM_SPLIT>>>(
        r, WlT, bl, nullptr, L, ND, ND, 0, 0, 0);

    // 3. G = r @ Wg + bg   (split-tf32)
    gemm_tt<true, true, false><<<dim3(NB * NM / 128, ND / 128, 1), 256, SMEM_SPLIT>>>(
        r, WgT, bg, nullptr, G, ND, ND, 0, 0, 0);

    // 4. GT[b][d][m]
    transpose_g_k<<<dim3(NM / 32, ND / 32, NB), dim3(32, 8)>>>(G, GT);

    // 5. scores[b][n][m] = sum_d H[b,n,d] * L[b,m,d]   (split-tf32, batched)
    gemm_tt<true, false, false><<<dim3(NN / 128, NM / 128, NB), 256, SMEM_SPLIT>>>(
        H, L, nullptr, nullptr, S, ND, NM,
        (long long)NN * ND, (long long)NM * ND, (long long)NN * NM);

    // 6. softmax over M (in place)
    softmax_k<<<NB * NN / 8, 256>>>(S);

    // 7. out = p + attn @ G   (plain tf32 is enough post-softmax; batched)
    gemm_tt<false, false, true><<<dim3(NN / 128, ND / 128, NB), 256, SMEM_PLAIN>>>(
        S, GT, nullptr, p, out, NM, ND,
        (long long)NN * NM, (long long)ND * NM, (long long)NN * ND);
}

// round 3
// speedup vs baseline: 1.0024x; 1.0024x over previous
#include <cuda_runtime.h>
#include <cstdint>

#define NB 8
#define NN 4096
#define NM 1024
#define ND 256

// ---------------- scratch (device globals; no runtime allocation) ----------------
static constexpr size_t OFF_WHT = 0;
static constexpr size_t OFF_WLT = OFF_WHT + (size_t)ND * ND;
static constexpr size_t OFF_WGT = OFF_WLT + (size_t)ND * ND;
static constexpr size_t OFF_H   = OFF_WGT + (size_t)ND * ND;
static constexpr size_t OFF_L   = OFF_H  + (size_t)NB * NN * ND;
static constexpr size_t OFF_G   = OFF_L  + (size_t)NB * NM * ND;
static constexpr size_t OFF_GT  = OFF_G  + (size_t)NB * NM * ND;
static constexpr size_t OFF_S   = OFF_GT + (size_t)NB * ND * NM;
static constexpr size_t SCRATCH_TOTAL = OFF_S + (size_t)NB * NN * NM;

__device__ float g_scratch[SCRATCH_TOTAL];

// ---------------- helpers ----------------
__device__ __forceinline__ uint32_t f2tf(float x) {
    uint32_t r;
    asm("cvt.rna.tf32.f32 %0, %1;" : "=r"(r) : "f"(x));
    return r;
}

#define MMA8(d, a, b)                                                          \
    asm volatile(                                                              \
        "mma.sync.aligned.m16n8k8.row.col.f32.tf32.tf32.f32 "                  \
        "{%0,%1,%2,%3},{%4,%5,%6,%7},{%8,%9},{%0,%1,%2,%3};\n"                 \
        : "+f"((d)[0]), "+f"((d)[1]), "+f"((d)[2]), "+f"((d)[3])               \
        : "r"((a)[0]), "r"((a)[1]), "r"((a)[2]), "r"((a)[3]),                  \
          "r"((b)[0]), "r"((b)[1]))

// ---------------- weight transpose: WT[n][k] = W[k][n] ----------------
__global__ void transpose_w_k(const float* __restrict__ Wh,
                              const float* __restrict__ Wl,
                              const float* __restrict__ Wg,
                              float* __restrict__ wht,
                              float* __restrict__ wlt,
                              float* __restrict__ wgt) {
    int i = blockIdx.x * blockDim.x + threadIdx.x;  // 65536 total
    int n = i >> 8, k = i & 255;
    wht[i] = Wh[k * ND + n];
    wlt[i] = Wl[k * ND + n];
    wgt[i] = Wg[k * ND + n];
}

// ---------------- G transpose: GT[b][d][m] = G[b][m][d] ----------------
__global__ void transpose_g_k(const float* __restrict__ G, float* __restrict__ GT) {
    __shared__ float t[32][33];
    int b = blockIdx.z;
    int m0 = blockIdx.x * 32, d0 = blockIdx.y * 32;
    const float* src = G + (size_t)b * NM * ND;
    float* dst = GT + (size_t)b * ND * NM;
    int x = threadIdx.x, y = threadIdx.y;
#pragma unroll
    for (int i = 0; i < 32; i += 8) t[y + i][x] = src[(size_t)(m0 + y + i) * ND + d0 + x];
    __syncthreads();
#pragma unroll
    for (int i = 0; i < 32; i += 8) dst[(size_t)(d0 + y + i) * NM + m0 + x] = t[x][y + i];
}

// ---------------- generic TT GEMM: C[row][col] = sum_k A[row][k] * Bsrc[col][k] ----------------
// A: [rows][K] row-major, Bsrc: [Ncols][K] row-major (both loaded identically).
// SPLIT: split-tf32 (3-MMA hi/lo) for ~fp32 accuracy. BIAS: +bias[col]. RESID: +R[row][col].
template <bool SPLIT, bool BIAS, bool RESID>
__global__ void __launch_bounds__(256)
gemm_tt(const float* __restrict__ Aptr, const float* __restrict__ Bptr,
        const float* __restrict__ bias, const float* __restrict__ Rptr,
        float* __restrict__ Cptr, int K, int Ncols,
        long long sA, long long sB, long long sC) {
    constexpr int BM = 128, BN = 128, BK = 32, LDSR = 36;  // pad -> conflict-free frag LDS
    extern __shared__ uint32_t smem_u[];
    uint32_t* As = smem_u;
    uint32_t* Bs = smem_u + BM * LDSR;
    uint32_t* Al = smem_u + 2 * BM * LDSR;  // only used when SPLIT
    uint32_t* Bl = smem_u + 3 * BM * LDSR;

    int tid = threadIdx.x;
    int lane = tid & 31, wid = tid >> 5;
    int wm = wid >> 1, wn = wid & 1;     // 4x2 warp grid; warp tile 32x64
    int grp = lane >> 2, tq = lane & 3;  // mma fragment coords

    long long zb = blockIdx.z;
    const float* A = Aptr + zb * sA + (long long)blockIdx.x * BM * K;
    const float* Bm = Bptr + zb * sB + (long long)blockIdx.y * BN * K;

    float acc[2][8][4];
#pragma unroll
    for (int i = 0; i < 2; i++)
#pragma unroll
        for (int j = 0; j < 8; j++)
#pragma unroll
            for (int q = 0; q < 4; q++) acc[i][j][q] = 0.f;

    for (int kc = 0; kc < K; kc += BK) {
        __syncthreads();
#pragma unroll
        for (int it = 0; it < 4; it++) {
            int idx = tid + it * 256;
            int rr = idx >> 3, cc = (idx & 7) * 4;
            float4 va = *(const float4*)(A + (long long)rr * K + kc + cc);
            float4 vb = *(const float4*)(Bm + (long long)rr * K + kc + cc);
            uint32_t* pa = As + rr * LDSR + cc;
            uint32_t* pb = Bs + rr * LDSR + cc;
            uint32_t h;
            h = f2tf(va.x); pa[0] = h; if (SPLIT) Al[rr * LDSR + cc + 0] = f2tf(va.x - __uint_as_float(h));
            h = f2tf(va.y); pa[1] = h; if (SPLIT) Al[rr * LDSR + cc + 1] = f2tf(va.y - __uint_as_float(h));
            h = f2tf(va.z); pa[2] = h; if (SPLIT) Al[rr * LDSR + cc + 2] = f2tf(va.z - __uint_as_float(h));
            h = f2tf(va.w); pa[3] = h; if (SPLIT) Al[rr * LDSR + cc + 3] = f2tf(va.w - __uint_as_float(h));
            h = f2tf(vb.x); pb[0] = h; if (SPLIT) Bl[rr * LDSR + cc + 0] = f2tf(vb.x - __uint_as_float(h));
            h = f2tf(vb.y); pb[1] = h; if (SPLIT) Bl[rr * LDSR + cc + 1] = f2tf(vb.y - __uint_as_float(h));
            h = f2tf(vb.z); pb[2] = h; if (SPLIT) Bl[rr * LDSR + cc + 2] = f2tf(vb.z - __uint_as_float(h));
            h = f2tf(vb.w); pb[3] = h; if (SPLIT) Bl[rr * LDSR + cc + 3] = f2tf(vb.w - __uint_as_float(h));
        }
        __syncthreads();
#pragma unroll
        for (int ks = 0; ks < 4; ks++) {
            int k0 = ks * 8;
            uint32_t a[2][4], al[2][4];
            uint32_t b[8][2], bl2[8][2];
#pragma unroll
            for (int i = 0; i < 2; i++) {
                int ro = (wm * 32 + i * 16 + grp) * LDSR + k0 + tq;
                a[i][0] = As[ro];
                a[i][1] = As[ro + 8 * LDSR];
                a[i][2] = As[ro + 4];
                a[i][3] = As[ro + 8 * LDSR + 4];
                if (SPLIT) {
                    al[i][0] = Al[ro];
                    al[i][1] = Al[ro + 8 * LDSR];
                    al[i][2] = Al[ro + 4];
                    al[i][3] = Al[ro + 8 * LDSR + 4];
                }
            }
#pragma unroll
            for (int j = 0; j < 8; j++) {
                int co = (wn * 64 + j * 8 + grp) * LDSR + k0 + tq;
                b[j][0] = Bs[co];
                b[j][1] = Bs[co + 4];
                if (SPLIT) {
                    bl2[j][0] = Bl[co];
                    bl2[j][1] = Bl[co + 4];
                }
            }
#pragma unroll
            for (int i = 0; i < 2; i++)
#pragma unroll
                for (int j = 0; j < 8; j++) {
                    if (SPLIT) {
                        MMA8(acc[i][j], al[i], b[j]);
                        MMA8(acc[i][j], a[i], bl2[j]);
                    }
                    MMA8(acc[i][j], a[i], b[j]);
                }
        }
    }

    // epilogue
    int row0 = blockIdx.x * BM + wm * 32 + grp;
    int col0 = blockIdx.y * BN + wn * 64 + 2 * tq;
    float* C = Cptr + zb * sC;
    const float* R = RESID ? (Rptr + zb * sC) : nullptr;
#pragma unroll
    for (int i = 0; i < 2; i++) {
#pragma unroll
        for (int j = 0; j < 8; j++) {
            int row = row0 + i * 16;
            int col = col0 + j * 8;
            float2 v0 = make_float2(acc[i][j][0], acc[i][j][1]);
            float2 v1 = make_float2(acc[i][j][2], acc[i][j][3]);
            if (BIAS) {
                float2 bb = *(const float2*)(bias + col);
                v0.x += bb.x; v0.y += bb.y;
                v1.x += bb.x; v1.y += bb.y;
            }
            if (RESID) {
                float2 r0 = *(const float2*)(R + (long long)row * Ncols + col);
                float2 r1 = *(const float2*)(R + (long long)(row + 8) * Ncols + col);
                v0.x += r0.x; v0.y += r0.y;
                v1.x += r1.x; v1.y += r1.y;
            }
            *(float2*)(C + (long long)row * Ncols + col) = v0;
            *(float2*)(C + (long long)(row + 8) * Ncols + col) = v1;
        }
    }
}

// ---------------- softmax over M: one warp per row ----------------
__global__ void softmax_k(float* __restrict__ S) {
    int row = blockIdx.x * 8 + (threadIdx.x >> 5);
    int lane = threadIdx.x & 31;
    float4* p4 = (float4*)(S + (size_t)row * NM) + lane;
    float4 v[8];
    float mx = -1e30f;
#pragma unroll
    for (int t = 0; t < 8; t++) {
        v[t] = p4[t * 32];
        mx = fmaxf(mx, fmaxf(fmaxf(v[t].x, v[t].y), fmaxf(v[t].z, v[t].w)));
    }
#pragma unroll
    for (int o = 16; o > 0; o >>= 1) mx = fmaxf(mx, __shfl_xor_sync(0xffffffffu, mx, o));
    float sum = 0.f;
#pragma unroll
    for (int t = 0; t < 8; t++) {
        v[t].x = __expf(v[t].x - mx);
        v[t].y = __expf(v[t].y - mx);
        v[t].z = __expf(v[t].z - mx);
        v[t].w = __expf(v[t].w - mx);
        sum += v[t].x + v[t].y + v[t].z + v[t].w;
    }
#pragma unroll
    for (int o = 16; o > 0; o >>= 1) sum += __shfl_xor_sync(0xffffffffu, sum, o);
    float inv = 1.0f / sum;
#pragma unroll
    for (int t = 0; t < 8; t++) {
        v[t].x *= inv; v[t].y *= inv; v[t].z *= inv; v[t].w *= inv;
        p4[t * 32] = v[t];
    }
}

// ---------------- launch ----------------
extern "C" void kernel_launch(void* const* d_in, const int* in_sizes, int n_in,
                              void* d_out, int out_size) {
    const float* p  = (const float*)d_in[0];
    const float* r  = (const float*)d_in[1];
    // d_in[2] = batch ids (int64) — unused (implied by layout)
    const float* Wh = (const float*)d_in[3];
    const float* bh = (const float*)d_in[4];
    const float* Wl = (const float*)d_in[5];
    const float* bl = (const float*)d_in[6];
    const float* Wg = (const float*)d_in[7];
    const float* bg = (const float*)d_in[8];
    float* out = (float*)d_out;
    (void)in_sizes; (void)n_in; (void)out_size;

    float* s = nullptr;
    cudaGetSymbolAddress((void**)&s, g_scratch);
    float* WhT = s + OFF_WHT;
    float* WlT = s + OFF_WLT;
    float* WgT = s + OFF_WGT;
    float* H   = s + OFF_H;
    float* L   = s + OFF_L;
    float* G   = s + OFF_G;
    float* GT  = s + OFF_GT;
    float* S   = s + OFF_S;

    const int SMEM_SPLIT = 4 * 128 * 36 * 4;  // 73728
    const int SMEM_PLAIN = 2 * 128 * 36 * 4;  // 36864
    cudaFuncSetAttribute(gemm_tt<true, true, false>,
                         cudaFuncAttributeMaxDynamicSharedMemorySize, SMEM_SPLIT);
    cudaFuncSetAttribute(gemm_tt<true, false, false>,
                         cudaFuncAttributeMaxDynamicSharedMemorySize, SMEM_SPLIT);
    cudaFuncSetAttribute(gemm_tt<false, false, true>,
                         cudaFuncAttributeMaxDynamicSharedMemorySize, SMEM_PLAIN);

    // 0. transpose weights -> [n][k]
    transpose_w_k<<<256, 256>>>(Wh, Wl, Wg, WhT, WlT, WgT);

    // 1. H = p @ Wh + bh   (split-tf32; rows = B*N)
    gemm_tt<true, true, false><<<dim3(NB * NN / 128, ND / 128, 1), 256, SMEM_SPLIT>>>(
        p, WhT, bh, nullptr, H, ND, ND, 0, 0, 0);

    // 2. L = r @ Wl + bl   (split-tf32; rows = B*M)
    gemm_tt<true, true, false><<<dim3(NB * NM / 128, ND / 128, 1), 256, SMEM_SPLIT>>>(
        r, WlT, bl, nullptr, L, ND, ND, 0, 0, 0);

    // 3. G = r @ Wg + bg   (split-tf32)
    gemm_tt<true, true, false><<<dim3(NB * NM / 128, ND / 128, 1), 256, SMEM_SPLIT>>>(
        r, WgT, bg, nullptr, G, ND, ND, 0, 0, 0);

    // 4. GT[b][d][m]
    transpose_g_k<<<dim3(NM / 32, ND / 32, NB), dim3(32, 8)>>>(G, GT);

    // 5. scores[b][n][m] = sum_d H[b,n,d] * L[b,m,d]   (split-tf32, batched)
    gemm_tt<true, false, false><<<dim3(NN / 128, NM / 128, NB), 256, SMEM_SPLIT>>>(
        H, L, nullptr, nullptr, S, ND, NM,
        (long long)NN * ND, (long long)NM * ND, (long long)NN * NM);

    // 6. softmax over M (in place)
    softmax_k<<<NB * NN / 8, 256>>>(S);

    // 7. out = p + attn @ G   (plain tf32 is enough post-softmax; batched)
    gemm_tt<false, false, true><<<dim3(NN / 128, ND / 128, NB), 256, SMEM_PLAIN>>>(
        S, GT, nullptr, p, out, NM, ND,
        (long long)NN * NM, (long long)ND * NM, (long long)NN * ND);
}

// round 4
// speedup vs baseline: 1.0025x; 1.0001x over previous
#include <cuda_runtime.h>
#include <cstdint>

#define NB 8
#define NN 4096
#define NM 1024
#define ND 256

// ---------------- scratch (device globals; no runtime allocation) ----------------
static constexpr size_t OFF_WHT = 0;
static constexpr size_t OFF_WLT = OFF_WHT + (size_t)ND * ND;
static constexpr size_t OFF_WGT = OFF_WLT + (size_t)ND * ND;
static constexpr size_t OFF_H   = OFF_WGT + (size_t)ND * ND;
static constexpr size_t OFF_L   = OFF_H  + (size_t)NB * NN * ND;
static constexpr size_t OFF_G   = OFF_L  + (size_t)NB * NM * ND;
static constexpr size_t OFF_GT  = OFF_G  + (size_t)NB * NM * ND;
static constexpr size_t OFF_S   = OFF_GT + (size_t)NB * ND * NM;
static constexpr size_t SCRATCH_TOTAL = OFF_S + (size_t)NB * NN * NM;

__device__ float g_scratch[SCRATCH_TOTAL];

// ---------------- helpers ----------------
__device__ __forceinline__ uint32_t f2tf(float x) {
    uint32_t r;
    asm("cvt.rna.tf32.f32 %0, %1;" : "=r"(r) : "f"(x));
    return r;
}

#define MMA8(d, a, b)                                                          \
    asm volatile(                                                              \
        "mma.sync.aligned.m16n8k8.row.col.f32.tf32.tf32.f32 "                  \
        "{%0,%1,%2,%3},{%4,%5,%6,%7},{%8,%9},{%0,%1,%2,%3};\n"                 \
        : "+f"((d)[0]), "+f"((d)[1]), "+f"((d)[2]), "+f"((d)[3])               \
        : "r"((a)[0]), "r"((a)[1]), "r"((a)[2]), "r"((a)[3]),                  \
          "r"((b)[0]), "r"((b)[1]))

// ---------------- weight transpose: WT[n][k] = W[k][n] ----------------
__global__ void transpose_w_k(const float* __restrict__ Wh,
                              const float* __restrict__ Wl,
                              const float* __restrict__ Wg,
                              float* __restrict__ wht,
                              float* __restrict__ wlt,
                              float* __restrict__ wgt) {
    int i = blockIdx.x * blockDim.x + threadIdx.x;  // 65536 total
    int n = i >> 8, k = i & 255;
    wht[i] = Wh[k * ND + n];
    wlt[i] = Wl[k * ND + n];
    wgt[i] = Wg[k * ND + n];
}

// ---------------- G transpose: GT[b][d][m] = G[b][m][d] ----------------
__global__ void transpose_g_k(const float* __restrict__ G, float* __restrict__ GT) {
    __shared__ float t[32][33];
    int b = blockIdx.z;
    int m0 = blockIdx.x * 32, d0 = blockIdx.y * 32;
    const float* src = G + (size_t)b * NM * ND;
    float* dst = GT + (size_t)b * ND * NM;
    int x = threadIdx.x, y = threadIdx.y;
#pragma unroll
    for (int i = 0; i < 32; i += 8) t[y + i][x] = src[(size_t)(m0 + y + i) * ND + d0 + x];
    __syncthreads();
#pragma unroll
    for (int i = 0; i < 32; i += 8) dst[(size_t)(d0 + y + i) * NM + m0 + x] = t[x][y + i];
}

// ---------------- generic TT GEMM: C[row][col] = sum_k A[row][k] * Bsrc[col][k] ----------------
// A: [rows][K] row-major, Bsrc: [Ncols][K] row-major (both loaded identically).
// SPLIT: split-tf32 (3-MMA hi/lo) for ~fp32 accuracy. BIAS: +bias[col]. RESID: +R[row][col].
template <bool SPLIT, bool BIAS, bool RESID>
__global__ void __launch_bounds__(256)
gemm_tt(const float* __restrict__ Aptr, const float* __restrict__ Bptr,
        const float* __restrict__ bias, const float* __restrict__ Rptr,
        float* __restrict__ Cptr, int K, int Ncols,
        long long sA, long long sB, long long sC) {
    constexpr int BM = 128, BN = 128, BK = 32, LDSR = 36;  // pad -> conflict-free frag LDS
    extern __shared__ uint32_t smem_u[];
    uint32_t* As = smem_u;
    uint32_t* Bs = smem_u + BM * LDSR;
    uint32_t* Al = smem_u + 2 * BM * LDSR;  // only used when SPLIT
    uint32_t* Bl = smem_u + 3 * BM * LDSR;

    int tid = threadIdx.x;
    int lane = tid & 31, wid = tid >> 5;
    int wm = wid >> 1, wn = wid & 1;     // 4x2 warp grid; warp tile 32x64
    int grp = lane >> 2, tq = lane & 3;  // mma fragment coords

    long long zb = blockIdx.z;
    const float* A = Aptr + zb * sA + (long long)blockIdx.x * BM * K;
    const float* Bm = Bptr + zb * sB + (long long)blockIdx.y * BN * K;

    float acc[2][8][4];
#pragma unroll
    for (int i = 0; i < 2; i++)
#pragma unroll
        for (int j = 0; j < 8; j++)
#pragma unroll
            for (int q = 0; q < 4; q++) acc[i][j][q] = 0.f;

    for (int kc = 0; kc < K; kc += BK) {
        __syncthreads();
#pragma unroll
        for (int it = 0; it < 4; it++) {
            int idx = tid + it * 256;
            int rr = idx >> 3, cc = (idx & 7) * 4;
            float4 va = *(const float4*)(A + (long long)rr * K + kc + cc);
            float4 vb = *(const float4*)(Bm + (long long)rr * K + kc + cc);
            uint32_t* pa = As + rr * LDSR + cc;
            uint32_t* pb = Bs + rr * LDSR + cc;
            uint32_t h;
            h = f2tf(va.x); pa[0] = h; if (SPLIT) Al[rr * LDSR + cc + 0] = f2tf(va.x - __uint_as_float(h));
            h = f2tf(va.y); pa[1] = h; if (SPLIT) Al[rr * LDSR + cc + 1] = f2tf(va.y - __uint_as_float(h));
            h = f2tf(va.z); pa[2] = h; if (SPLIT) Al[rr * LDSR + cc + 2] = f2tf(va.z - __uint_as_float(h));
            h = f2tf(va.w); pa[3] = h; if (SPLIT) Al[rr * LDSR + cc + 3] = f2tf(va.w - __uint_as_float(h));
            h = f2tf(vb.x); pb[0] = h; if (SPLIT) Bl[rr * LDSR + cc + 0] = f2tf(vb.x - __uint_as_float(h));
            h = f2tf(vb.y); pb[1] = h; if (SPLIT) Bl[rr * LDSR + cc + 1] = f2tf(vb.y - __uint_as_float(h));
            h = f2tf(vb.z); pb[2] = h; if (SPLIT) Bl[rr * LDSR + cc + 2] = f2tf(vb.z - __uint_as_float(h));
            h = f2tf(vb.w); pb[3] = h; if (SPLIT) Bl[rr * LDSR + cc + 3] = f2tf(vb.w - __uint_as_float(h));
        }
        __syncthreads();
#pragma unroll
        for (int ks = 0; ks < 4; ks++) {
            int k0 = ks * 8;
            uint32_t a[2][4], al[2][4];
            uint32_t b[8][2], bl2[8][2];
#pragma unroll
            for (int i = 0; i < 2; i++) {
                int ro = (wm * 32 + i * 16 + grp) * LDSR + k0 + tq;
                a[i][0] = As[ro];
                a[i][1] = As[ro + 8 * LDSR];
                a[i][2] = As[ro + 4];
                a[i][3] = As[ro + 8 * LDSR + 4];
                if (SPLIT) {
                    al[i][0] = Al[ro];
                    al[i][1] = Al[ro + 8 * LDSR];
                    al[i][2] = Al[ro + 4];
                    al[i][3] = Al[ro + 8 * LDSR + 4];
                }
            }
#pragma unroll
            for (int j = 0; j < 8; j++) {
                int co = (wn * 64 + j * 8 + grp) * LDSR + k0 + tq;
                b[j][0] = Bs[co];
                b[j][1] = Bs[co + 4];
                if (SPLIT) {
                    bl2[j][0] = Bl[co];
                    bl2[j][1] = Bl[co + 4];
                }
            }
#pragma unroll
            for (int i = 0; i < 2; i++)
#pragma unroll
                for (int j = 0; j < 8; j++) {
                    if (SPLIT) {
                        MMA8(acc[i][j], al[i], b[j]);
                        MMA8(acc[i][j], a[i], bl2[j]);
                    }
                    MMA8(acc[i][j], a[i], b[j]);
                }
        }
    }

    // epilogue
    int row0 = blockIdx.x * BM + wm * 32 + grp;
    int col0 = blockIdx.y * BN + wn * 64 + 2 * tq;
    float* C = Cptr + zb * sC;
    const float* R = RESID ? (Rptr + zb * sC) : nullptr;
#pragma unroll
    for (int i = 0; i < 2; i++) {
#pragma unroll
        for (int j = 0; j < 8; j++) {
            int row = row0 + i * 16;
            int col = col0 + j * 8;
            float2 v0 = make_float2(acc[i][j][0], acc[i][j][1]);
            float2 v1 = make_float2(acc[i][j][2], acc[i][j][3]);
            if (BIAS) {
                float2 bb = *(const float2*)(bias + col);
                v0.x += bb.x; v0.y += bb.y;
                v1.x += bb.x; v1.y += bb.y;
            }
            if (RESID) {
                float2 r0 = *(const float2*)(R + (long long)row * Ncols + col);
                float2 r1 = *(const float2*)(R + (long long)(row + 8) * Ncols + col);
                v0.x += r0.x; v0.y += r0.y;
                v1.x += r1.x; v1.y += r1.y;
            }
            *(float2*)(C + (long long)row * Ncols + col) = v0;
            *(float2*)(C + (long long)(row + 8) * Ncols + col) = v1;
        }
    }
}

// ---------------- softmax over M: one warp per row ----------------
__global__ void softmax_k(float* __restrict__ S) {
    int row = blockIdx.x * 8 + (threadIdx.x >> 5);
    int lane = threadIdx.x & 31;
    float4* p4 = (float4*)(S + (size_t)row * NM) + lane;
    float4 v[8];
    float mx = -1e30f;
#pragma unroll
    for (int t = 0; t < 8; t++) {
        v[t] = p4[t * 32];
        mx = fmaxf(mx, fmaxf(fmaxf(v[t].x, v[t].y), fmaxf(v[t].z, v[t].w)));
    }
#pragma unroll
    for (int o = 16; o > 0; o >>= 1) mx = fmaxf(mx, __shfl_xor_sync(0xffffffffu, mx, o));
    float sum = 0.f;
#pragma unroll
    for (int t = 0; t < 8; t++) {
        v[t].x = __expf(v[t].x - mx);
        v[t].y = __expf(v[t].y - mx);
        v[t].z = __expf(v[t].z - mx);
        v[t].w = __expf(v[t].w - mx);
        sum += v[t].x + v[t].y + v[t].z + v[t].w;
    }
#pragma unroll
    for (int o = 16; o > 0; o >>= 1) sum += __shfl_xor_sync(0xffffffffu, sum, o);
    float inv = 1.0f / sum;
#pragma unroll
    for (int t = 0; t < 8; t++) {
        v[t].x *= inv; v[t].y *= inv; v[t].z *= inv; v[t].w *= inv;
        p4[t * 32] = v[t];
    }
}

// ---------------- launch ----------------
extern "C" void kernel_launch(void* const* d_in, const int* in_sizes, int n_in,
                              void* d_out, int out_size) {
    const float* p  = (const float*)d_in[0];
    const float* r  = (const float*)d_in[1];
    // d_in[2] = batch ids (int64) — unused (implied by layout)
    const float* Wh = (const float*)d_in[3];
    const float* bh = (const float*)d_in[4];
    const float* Wl = (const float*)d_in[5];
    const float* bl = (const float*)d_in[6];
    const float* Wg = (const float*)d_in[7];
    const float* bg = (const float*)d_in[8];
    float* out = (float*)d_out;
    (void)in_sizes; (void)n_in; (void)out_size;

    float* s = nullptr;
    cudaGetSymbolAddress((void**)&s, g_scratch);
    float* WhT = s + OFF_WHT;
    float* WlT = s + OFF_WLT;
    float* WgT = s + OFF_WGT;
    float* H   = s + OFF_H;
    float* L   = s + OFF_L;
    float* G   = s + OFF_G;
    float* GT  = s + OFF_GT;
    float* S   = s + OFF_S;

    const int SMEM_SPLIT = 4 * 128 * 36 * 4;  // 73728
    const int SMEM_PLAIN = 2 * 128 * 36 * 4;  // 36864
    cudaFuncSetAttribute(gemm_tt<true, true, false>,
                         cudaFuncAttributeMaxDynamicSharedMemorySize, SMEM_SPLIT);
    cudaFuncSetAttribute(gemm_tt<true, false, false>,
                         cudaFuncAttributeMaxDynamicSharedMemorySize, SMEM_SPLIT);
    cudaFuncSetAttribute(gemm_tt<false, false, true>,
                         cudaFuncAttributeMaxDynamicSharedMemorySize, SMEM_PLAIN);

    // 0. transpose weights -> [n][k]
    transpose_w_k<<<256, 256>>>(Wh, Wl, Wg, WhT, WlT, WgT);

    // 1. H = p @ Wh + bh   (split-tf32; rows = B*N)
    gemm_tt<true, true, false><<<dim3(NB * NN / 128, ND / 128, 1), 256, SMEM_SPLIT>>>(
        p, WhT, bh, nullptr, H, ND, ND, 0, 0, 0);

    // 2. L = r @ Wl + bl   (split-tf32; rows = B*M)
    gemm_tt<true, true, false><<<dim3(NB * NM / 128, ND / 128, 1), 256, SMEM_SPLIT>>>(
        r, WlT, bl, nullptr, L, ND, ND, 0, 0, 0);

    // 3. G = r @ Wg + bg   (split-tf32)
    gemm_tt<true, true, false><<<dim3(NB * NM / 128, ND / 128, 1), 256, SMEM_SPLIT>>>(
        r, WgT, bg, nullptr, G, ND, ND, 0, 0, 0);

    // 4. GT[b][d][m]
    transpose_g_k<<<dim3(NM / 32, ND / 32, NB), dim3(32, 8)>>>(G, GT);

    // 5. scores[b][n][m] = sum_d H[b,n,d] * L[b,m,d]   (split-tf32, batched)
    gemm_tt<true, false, false><<<dim3(NN / 128, NM / 128, NB), 256, SMEM_SPLIT>>>(
        H, L, nullptr, nullptr, S, ND, NM,
        (long long)NN * ND, (long long)NM * ND, (long long)NN * NM);

    // 6. softmax over M (in place)
    softmax_k<<<NB * NN / 8, 256>>>(S);

    // 7. out = p + attn @ G   (plain tf32 is enough post-softmax; batched)
    gemm_tt<false, false, true><<<dim3(NN / 128, ND / 128, NB), 256, SMEM_PLAIN>>>(
        S, GT, nullptr, p, out, NM, ND,
        (long long)NN * NM, (long long)ND * NM, (long long)NN * ND);
}